// round 1
// baseline (speedup 1.0000x reference)
#include <cuda_runtime.h>
#include <cuda_bf16.h>
#include <math.h>

#define NN 20000
#define ETOT 150000
#define LPART 75000
#define FINC 256
#define HC 512
#define H2C 1024

// ---------------- static device scratch (no runtime alloc allowed) ----------------
__device__ float g_sf[NN * HC];
__device__ float g_df[NN * HC];
__device__ float g_out[NN * HC];
__device__ float g_h[NN * H2C];
__device__ float g_y[NN * HC];
__device__ float g_x1[NN * HC];
__device__ int g_rowptr[2][NN + 1];
__device__ int g_cursor[2][NN];
__device__ int g_eidx[2][LPART];

// ---------------- small utility kernels ----------------
__global__ void k_zero_int(int* p, int n) {
    int i = blockIdx.x * blockDim.x + threadIdx.x;
    if (i < n) p[i] = 0;
}

__global__ void k_count_deg(const int* __restrict__ dst, int L, int* __restrict__ deg) {
    int i = blockIdx.x * blockDim.x + threadIdx.x;
    if (i < L) atomicAdd(&deg[dst[i]], 1);
}

// single-block inclusive scan over n counts -> exclusive rowptr (n+1)
__global__ void k_scan(const int* __restrict__ deg, int* __restrict__ rowptr, int n) {
    __shared__ int sbuf[1024];
    __shared__ int carry;
    int t = threadIdx.x;
    if (t == 0) { carry = 0; rowptr[0] = 0; }
    __syncthreads();
    for (int base = 0; base < n; base += 1024) {
        int v = (base + t < n) ? deg[base + t] : 0;
        sbuf[t] = v;
        __syncthreads();
        for (int off = 1; off < 1024; off <<= 1) {
            int nv = (t >= off) ? sbuf[t - off] : 0;
            __syncthreads();
            sbuf[t] += nv;
            __syncthreads();
        }
        if (base + t < n) rowptr[base + t + 1] = carry + sbuf[t];
        __syncthreads();
        if (t == 0) carry += sbuf[1023];
        __syncthreads();
    }
}

__global__ void k_copy_int(const int* __restrict__ a, int* __restrict__ b, int n) {
    int i = blockIdx.x * blockDim.x + threadIdx.x;
    if (i < n) b[i] = a[i];
}

__global__ void k_scatter(const int* __restrict__ dst, int L, int* __restrict__ cursor,
                          int* __restrict__ eidx) {
    int i = blockIdx.x * blockDim.x + threadIdx.x;
    if (i < L) {
        int pos = atomicAdd(&cursor[dst[i]], 1);
        eidx[pos] = i;
    }
}

// deterministic edge order within each bucket (insertion sort; avg degree ~3.75)
__global__ void k_sort_buckets(const int* __restrict__ rowptr, int* __restrict__ eidx) {
    int node = blockIdx.x * blockDim.x + threadIdx.x;
    if (node >= NN) return;
    int a = rowptr[node], b = rowptr[node + 1];
    for (int i = a + 1; i < b; i++) {
        int key = eidx[i];
        int j = i - 1;
        while (j >= a && eidx[j] > key) { eidx[j + 1] = eidx[j]; j--; }
        eidx[j + 1] = key;
    }
}

__global__ void k_leaky(const float* __restrict__ y, float* __restrict__ x1, int n) {
    int i = blockIdx.x * blockDim.x + threadIdx.x;
    if (i < n) {
        float v = y[i];
        x1[i] = v > 0.f ? v : 0.01f * v;
    }
}

// ---------------- fused per-node edge softmax aggregation ----------------
// One warp per node; 16 h-elements per lane (H=512). Online softmax (max/sum-exp/
// sum-msg-exp) recomputing msg = relu(sf[src] + ea*We) + 1e-7 on the fly.
// out[d] = num/(den+1e-16) + df[d]
__global__ __launch_bounds__(128) void k_agg(
    const float* __restrict__ sfeat, const float* __restrict__ dfeat,
    const float* __restrict__ We, const float* __restrict__ ea,
    const int* __restrict__ srcIdx, const int* __restrict__ rowptr,
    const int* __restrict__ eidx, float* __restrict__ outp)
{
    __shared__ float wsh[HC];
    int t = threadIdx.x;
    for (int i = t; i < HC; i += 128) wsh[i] = We[i];
    __syncthreads();
    int warp = t >> 5, lane = t & 31;
    int node = blockIdx.x * 4 + warp;
    if (node >= NN) return;

    float wv[16];
#pragma unroll
    for (int j = 0; j < 16; j++) wv[j] = wsh[lane + 32 * j];

    float m[16], s[16], tt[16];
#pragma unroll
    for (int j = 0; j < 16; j++) { m[j] = -INFINITY; s[j] = 0.f; tt[j] = 0.f; }

    int e0 = rowptr[node], e1 = rowptr[node + 1];
    for (int e = e0; e < e1; e++) {
        int eid = eidx[e];
        int sidx = srcIdx[eid];
        float a = ea[eid];
        const float* row = sfeat + (size_t)sidx * HC;
#pragma unroll
        for (int j = 0; j < 16; j++) {
            float msg = fmaxf(row[lane + 32 * j] + a * wv[j], 0.f) + 1e-7f;
            float mn = fmaxf(m[j], msg);
            float scale = __expf(m[j] - mn);
            float p = __expf(msg - mn);
            s[j] = s[j] * scale + p;
            tt[j] = tt[j] * scale + msg * p;
            m[j] = mn;
        }
    }
    float* orow = outp + (size_t)node * HC;
    const float* drow = dfeat + (size_t)node * HC;
#pragma unroll
    for (int j = 0; j < 16; j++)
        orow[lane + 32 * j] = tt[j] / (s[j] + 1e-16f) + drow[lane + 32 * j];
}

// ---------------- SGEMM (NT): C[M,Nc] = A[M,K] @ B[Nc,K]^T ----------------
// 128x128 tile, BK=8, 256 threads, 8x8 per thread.
// mode 0: plain; mode 1: BN+ReLU epilogue ((acc-m)*g*rsqrt(v+eps)+b, relu)
// accum: C += result instead of C = result
#define BM 128
#define BN 128
#define BK 8

__global__ __launch_bounds__(256) void k_sgemm_nt(
    const float* __restrict__ A, const float* __restrict__ B, float* __restrict__ C,
    int M, int Ncols, int K, int mode,
    const float* __restrict__ gv, const float* __restrict__ bv,
    const float* __restrict__ mv, const float* __restrict__ vv, int accum)
{
    __shared__ float As[BK][BM];
    __shared__ float Bs[BK][BN];
    int tid = threadIdx.x;
    int tileM = blockIdx.y * BM, tileN = blockIdx.x * BN;

    int arow = tid >> 1;
    int ac4 = (tid & 1) * 4;
    bool avalid = (tileM + arow) < M;
    const float* Aptr = A + (size_t)(tileM + arow) * K + ac4;
    const float* Bptr = B + (size_t)(tileN + arow) * K + ac4;  // Ncols multiple of 128

    int ty = tid >> 4, tx = tid & 15;
    float acc[8][8];
#pragma unroll
    for (int i = 0; i < 8; i++)
#pragma unroll
        for (int j = 0; j < 8; j++) acc[i][j] = 0.f;

    for (int k0 = 0; k0 < K; k0 += BK) {
        float4 av = avalid ? *(const float4*)(Aptr + k0) : make_float4(0.f, 0.f, 0.f, 0.f);
        float4 bw = *(const float4*)(Bptr + k0);
        As[ac4 + 0][arow] = av.x; As[ac4 + 1][arow] = av.y;
        As[ac4 + 2][arow] = av.z; As[ac4 + 3][arow] = av.w;
        Bs[ac4 + 0][arow] = bw.x; Bs[ac4 + 1][arow] = bw.y;
        Bs[ac4 + 2][arow] = bw.z; Bs[ac4 + 3][arow] = bw.w;
        __syncthreads();
#pragma unroll
        for (int kk = 0; kk < BK; kk++) {
            float4 a0 = *(const float4*)&As[kk][ty * 8];
            float4 a1 = *(const float4*)&As[kk][ty * 8 + 4];
            float4 b0 = *(const float4*)&Bs[kk][tx * 8];
            float4 b1 = *(const float4*)&Bs[kk][tx * 8 + 4];
            float ar[8] = {a0.x, a0.y, a0.z, a0.w, a1.x, a1.y, a1.z, a1.w};
            float br[8] = {b0.x, b0.y, b0.z, b0.w, b1.x, b1.y, b1.z, b1.w};
#pragma unroll
            for (int i = 0; i < 8; i++)
#pragma unroll
                for (int j = 0; j < 8; j++)
                    acc[i][j] = fmaf(ar[i], br[j], acc[i][j]);
        }
        __syncthreads();
    }

    float cs[8], cb[8], cm[8];
    if (mode == 1) {
#pragma unroll
        for (int jj = 0; jj < 8; jj++) {
            int j = tileN + tx * 8 + jj;
            cs[jj] = gv[j] * rsqrtf(vv[j] + 1e-5f);
            cb[jj] = bv[j];
            cm[jj] = mv[j];
        }
    }
#pragma unroll
    for (int ii = 0; ii < 8; ii++) {
        int r = tileM + ty * 8 + ii;
        if (r >= M) continue;
        float* crow = C + (size_t)r * Ncols + tileN + tx * 8;
#pragma unroll
        for (int jj = 0; jj < 8; jj++) {
            float val = acc[ii][jj];
            if (mode == 1) val = fmaxf((val - cm[jj]) * cs[jj] + cb[jj], 0.f);
            if (accum) crow[jj] += val; else crow[jj] = val;
        }
    }
}

// ---------------- host orchestration ----------------
extern "C" void kernel_launch(void* const* d_in, const int* in_sizes, int n_in,
                              void* d_out, int out_size) {
    // input mapping (len0/len1 may or may not appear as scalar tensors)
    const float* x  = (const float*)d_in[0];
    const int*   ei = (const int*)d_in[1];
    const float* ea = (const float*)d_in[2];
    int base = 3;
    if (n_in > 19) base = 3 + (n_in - 19);  // skip len0/len1 scalars if present
    const float* l0_src  = (const float*)d_in[base + 0];
    const float* l0_dst  = (const float*)d_in[base + 1];
    const float* l0_edge = (const float*)d_in[base + 2];
    const float* l0_w1   = (const float*)d_in[base + 3];
    const float* l0_g    = (const float*)d_in[base + 4];
    const float* l0_b    = (const float*)d_in[base + 5];
    const float* l0_m    = (const float*)d_in[base + 6];
    const float* l0_v    = (const float*)d_in[base + 7];
    const float* l0_w2   = (const float*)d_in[base + 8];
    const float* l1_edge = (const float*)d_in[base + 9];
    const float* l1_w1   = (const float*)d_in[base + 10];
    const float* l1_g    = (const float*)d_in[base + 11];
    const float* l1_b    = (const float*)d_in[base + 12];
    const float* l1_m    = (const float*)d_in[base + 13];
    const float* l1_v    = (const float*)d_in[base + 14];
    const float* l1_w2   = (const float*)d_in[base + 15];
    float* out = (float*)d_out;

    float *sf, *df, *ob, *hb, *yb, *x1b;
    int *rowptr, *cursor, *eidx;
    cudaGetSymbolAddress((void**)&sf, g_sf);
    cudaGetSymbolAddress((void**)&df, g_df);
    cudaGetSymbolAddress((void**)&ob, g_out);
    cudaGetSymbolAddress((void**)&hb, g_h);
    cudaGetSymbolAddress((void**)&yb, g_y);
    cudaGetSymbolAddress((void**)&x1b, g_x1);
    cudaGetSymbolAddress((void**)&rowptr, g_rowptr);
    cudaGetSymbolAddress((void**)&cursor, g_cursor);
    cudaGetSymbolAddress((void**)&eidx, g_eidx);

    const int offs[2] = {0, LPART};

    // ---- build CSR-by-dst for both edge partitions ----
    for (int p = 0; p < 2; p++) {
        int* rp = rowptr + p * (NN + 1);
        int* cu = cursor + p * NN;
        int* ex = eidx + p * LPART;
        const int* dstp = ei + ETOT + offs[p];
        k_zero_int<<<(NN + 255) / 256, 256>>>(cu, NN);
        k_count_deg<<<(LPART + 255) / 256, 256>>>(dstp, LPART, cu);
        k_scan<<<1, 1024>>>(cu, rp, NN);
        k_copy_int<<<(NN + 255) / 256, 256>>>(rp, cu, NN);
        k_scatter<<<(LPART + 255) / 256, 256>>>(dstp, LPART, cu, ex);
        k_sort_buckets<<<(NN + 127) / 128, 128>>>(rp, ex);
    }

    dim3 blk(256);
    int gy = (NN + BM - 1) / BM;  // 157
    dim3 g512(HC / BN, gy), g1024(H2C / BN, gy);

    // ---- layer 0 ----
    for (int l = 0; l < 2; l++) {
        k_sgemm_nt<<<g512, blk>>>(x, l0_src + (size_t)l * HC * FINC, sf,
                                  NN, HC, FINC, 0, nullptr, nullptr, nullptr, nullptr, 0);
        k_sgemm_nt<<<g512, blk>>>(x, l0_dst + (size_t)l * HC * FINC, df,
                                  NN, HC, FINC, 0, nullptr, nullptr, nullptr, nullptr, 0);
        k_agg<<<(NN + 3) / 4, 128>>>(sf, df, l0_edge + (size_t)l * HC, ea + offs[l],
                                     ei + offs[l], rowptr + l * (NN + 1),
                                     eidx + l * LPART, ob);
        k_sgemm_nt<<<g1024, blk>>>(ob, l0_w1 + (size_t)l * H2C * HC, hb,
                                   NN, H2C, HC, 1,
                                   l0_g + l * H2C, l0_b + l * H2C,
                                   l0_m + l * H2C, l0_v + l * H2C, 0);
        k_sgemm_nt<<<g512, blk>>>(hb, l0_w2 + (size_t)l * HC * H2C, yb,
                                  NN, HC, H2C, 0, nullptr, nullptr, nullptr, nullptr, l > 0);
    }

    k_leaky<<<(NN * HC + 255) / 256, 256>>>(yb, x1b, NN * HC);

    // ---- layer 1 (no src/dst projections: sf = df = x1) ----
    for (int l = 0; l < 2; l++) {
        k_agg<<<(NN + 3) / 4, 128>>>(x1b, x1b, l1_edge + (size_t)l * HC, ea + offs[l],
                                     ei + offs[l], rowptr + l * (NN + 1),
                                     eidx + l * LPART, ob);
        k_sgemm_nt<<<g1024, blk>>>(ob, l1_w1 + (size_t)l * H2C * HC, hb,
                                   NN, H2C, HC, 1,
                                   l1_g + l * H2C, l1_b + l * H2C,
                                   l1_m + l * H2C, l1_v + l * H2C, 0);
        k_sgemm_nt<<<g512, blk>>>(hb, l1_w2 + (size_t)l * HC * H2C, out,
                                  NN, HC, H2C, 0, nullptr, nullptr, nullptr, nullptr, l > 0);
    }
}

// round 2
// speedup vs baseline: 2.5793x; 2.5793x over previous
#include <cuda_runtime.h>
#include <cuda_bf16.h>
#include <math.h>
#include <stdint.h>

#define NN 20000
#define ETOT 150000
#define LPART 75000
#define FINC 256
#define HC 512
#define H2C 1024

// ---------------- static device scratch (no runtime alloc allowed) ----------------
__device__ float g_sf[NN * HC];
__device__ float g_df[NN * HC];
__device__ float g_out[NN * HC];
__device__ float g_h[NN * H2C];
__device__ float g_y[NN * HC];
__device__ float g_x1[NN * HC];
__device__ int g_rowptr[2][NN + 1];
__device__ int g_cursor[2][NN];
__device__ int g_eidx[2][LPART];

// ---------------- small utility kernels ----------------
__global__ void k_zero_int(int* p, int n) {
    int i = blockIdx.x * blockDim.x + threadIdx.x;
    if (i < n) p[i] = 0;
}

__global__ void k_count_deg(const int* __restrict__ dst, int L, int* __restrict__ deg) {
    int i = blockIdx.x * blockDim.x + threadIdx.x;
    if (i < L) atomicAdd(&deg[dst[i]], 1);
}

// single-block inclusive scan over n counts -> exclusive rowptr (n+1)
__global__ void k_scan(const int* __restrict__ deg, int* __restrict__ rowptr, int n) {
    __shared__ int sbuf[1024];
    __shared__ int carry;
    int t = threadIdx.x;
    if (t == 0) { carry = 0; rowptr[0] = 0; }
    __syncthreads();
    for (int base = 0; base < n; base += 1024) {
        int v = (base + t < n) ? deg[base + t] : 0;
        sbuf[t] = v;
        __syncthreads();
        for (int off = 1; off < 1024; off <<= 1) {
            int nv = (t >= off) ? sbuf[t - off] : 0;
            __syncthreads();
            sbuf[t] += nv;
            __syncthreads();
        }
        if (base + t < n) rowptr[base + t + 1] = carry + sbuf[t];
        __syncthreads();
        if (t == 0) carry += sbuf[1023];
        __syncthreads();
    }
}

__global__ void k_copy_int(const int* __restrict__ a, int* __restrict__ b, int n) {
    int i = blockIdx.x * blockDim.x + threadIdx.x;
    if (i < n) b[i] = a[i];
}

__global__ void k_scatter(const int* __restrict__ dst, int L, int* __restrict__ cursor,
                          int* __restrict__ eidx) {
    int i = blockIdx.x * blockDim.x + threadIdx.x;
    if (i < L) {
        int pos = atomicAdd(&cursor[dst[i]], 1);
        eidx[pos] = i;
    }
}

// deterministic edge order within each bucket (insertion sort; avg degree ~3.75)
__global__ void k_sort_buckets(const int* __restrict__ rowptr, int* __restrict__ eidx) {
    int node = blockIdx.x * blockDim.x + threadIdx.x;
    if (node >= NN) return;
    int a = rowptr[node], b = rowptr[node + 1];
    for (int i = a + 1; i < b; i++) {
        int key = eidx[i];
        int j = i - 1;
        while (j >= a && eidx[j] > key) { eidx[j + 1] = eidx[j]; j--; }
        eidx[j + 1] = key;
    }
}

__global__ void k_leaky(const float* __restrict__ y, float* __restrict__ x1, int n) {
    int i = blockIdx.x * blockDim.x + threadIdx.x;
    if (i < n) {
        float v = y[i];
        x1[i] = v > 0.f ? v : 0.01f * v;
    }
}

// ---------------- fused per-node edge softmax aggregation ----------------
__global__ __launch_bounds__(128) void k_agg(
    const float* __restrict__ sfeat, const float* __restrict__ dfeat,
    const float* __restrict__ We, const float* __restrict__ ea,
    const int* __restrict__ srcIdx, const int* __restrict__ rowptr,
    const int* __restrict__ eidx, float* __restrict__ outp)
{
    __shared__ float wsh[HC];
    int t = threadIdx.x;
    for (int i = t; i < HC; i += 128) wsh[i] = We[i];
    __syncthreads();
    int warp = t >> 5, lane = t & 31;
    int node = blockIdx.x * 4 + warp;
    if (node >= NN) return;

    float wv[16];
#pragma unroll
    for (int j = 0; j < 16; j++) wv[j] = wsh[lane + 32 * j];

    float m[16], s[16], tt[16];
#pragma unroll
    for (int j = 0; j < 16; j++) { m[j] = -INFINITY; s[j] = 0.f; tt[j] = 0.f; }

    int e0 = rowptr[node], e1 = rowptr[node + 1];
    for (int e = e0; e < e1; e++) {
        int eid = eidx[e];
        int sidx = srcIdx[eid];
        float a = ea[eid];
        const float* row = sfeat + (size_t)sidx * HC;
#pragma unroll
        for (int j = 0; j < 16; j++) {
            float msg = fmaxf(row[lane + 32 * j] + a * wv[j], 0.f) + 1e-7f;
            float mn = fmaxf(m[j], msg);
            float scale = __expf(m[j] - mn);
            float p = __expf(msg - mn);
            s[j] = s[j] * scale + p;
            tt[j] = tt[j] * scale + msg * p;
            m[j] = mn;
        }
    }
    float* orow = outp + (size_t)node * HC;
    const float* drow = dfeat + (size_t)node * HC;
#pragma unroll
    for (int j = 0; j < 16; j++)
        orow[lane + 32 * j] = tt[j] / (s[j] + 1e-16f) + drow[lane + 32 * j];
}

// ---------------- TF32 tensor-core GEMM (NT): C[M,Nc] = A[M,K] @ B[Nc,K]^T ---------
// Block tile 128x128x32, 256 threads (8 warps), warp tile 64x32 (4x4 m16n8k8 atoms).
// mode 0: plain; mode 1: BN+ReLU epilogue. accum: C += result.
#define BM 128
#define BN 128
#define BK 32
#define BKP (BK + 4)

__device__ __forceinline__ uint32_t f2tf(float f) {
    uint32_t r;
    asm("cvt.rna.tf32.f32 %0, %1;" : "=r"(r) : "f"(f));
    return r;
}

__device__ __forceinline__ void mma_tf32(float* c, const uint32_t* a, uint32_t b0, uint32_t b1) {
    asm volatile(
        "mma.sync.aligned.m16n8k8.row.col.f32.tf32.tf32.f32 "
        "{%0,%1,%2,%3}, {%4,%5,%6,%7}, {%8,%9}, {%0,%1,%2,%3};"
        : "+f"(c[0]), "+f"(c[1]), "+f"(c[2]), "+f"(c[3])
        : "r"(a[0]), "r"(a[1]), "r"(a[2]), "r"(a[3]), "r"(b0), "r"(b1));
}

__global__ __launch_bounds__(256) void k_mma_nt(
    const float* __restrict__ A, const float* __restrict__ B, float* __restrict__ C,
    int M, int Ncols, int K, int mode,
    const float* __restrict__ gv, const float* __restrict__ bv,
    const float* __restrict__ mv, const float* __restrict__ vv, int accum)
{
    __shared__ uint32_t As[BM][BKP];
    __shared__ uint32_t Bs[BN][BKP];

    int tid = threadIdx.x;
    int tileM = blockIdx.y * BM, tileN = blockIdx.x * BN;
    int warp = tid >> 5, lane = tid & 31;
    int g8 = lane >> 2, t4 = lane & 3;
    int wm = (warp & 1) * 64;
    int wn = (warp >> 1) * 32;

    // global staging: each thread owns 4 rows (it*32 + tid>>3) at f4-col tid&7
    int lrow = tid >> 3;      // 0..31
    int lc4 = (tid & 7) * 4;  // float col within k-tile

    float4 sa[4], sb[4];
    const float4 z4 = make_float4(0.f, 0.f, 0.f, 0.f);

    float acc[4][4][4];
#pragma unroll
    for (int i = 0; i < 4; i++)
#pragma unroll
        for (int j = 0; j < 4; j++)
#pragma unroll
            for (int r = 0; r < 4; r++) acc[i][j][r] = 0.f;

    // load first k-tile into regs
#pragma unroll
    for (int it = 0; it < 4; it++) {
        int row = it * 32 + lrow;
        sa[it] = (tileM + row < M) ? *(const float4*)(A + (size_t)(tileM + row) * K + lc4) : z4;
        sb[it] = *(const float4*)(B + (size_t)(tileN + row) * K + lc4);
    }
    // store (with tf32 rounding)
#pragma unroll
    for (int it = 0; it < 4; it++) {
        int row = it * 32 + lrow;
        uint4 pa = make_uint4(f2tf(sa[it].x), f2tf(sa[it].y), f2tf(sa[it].z), f2tf(sa[it].w));
        uint4 pb = make_uint4(f2tf(sb[it].x), f2tf(sb[it].y), f2tf(sb[it].z), f2tf(sb[it].w));
        *(uint4*)&As[row][lc4] = pa;
        *(uint4*)&Bs[row][lc4] = pb;
    }
    __syncthreads();

    for (int k0 = 0; k0 < K; k0 += BK) {
        bool has_next = (k0 + BK) < K;
        if (has_next) {
#pragma unroll
            for (int it = 0; it < 4; it++) {
                int row = it * 32 + lrow;
                sa[it] = (tileM + row < M)
                             ? *(const float4*)(A + (size_t)(tileM + row) * K + k0 + BK + lc4)
                             : z4;
                sb[it] = *(const float4*)(B + (size_t)(tileN + row) * K + k0 + BK + lc4);
            }
        }

#pragma unroll
        for (int kk = 0; kk < 4; kk++) {
            int kb = kk * 8;
            uint32_t af[4][4];
#pragma unroll
            for (int i = 0; i < 4; i++) {
                int r0 = wm + i * 16 + g8;
                af[i][0] = As[r0][kb + t4];
                af[i][1] = As[r0 + 8][kb + t4];
                af[i][2] = As[r0][kb + t4 + 4];
                af[i][3] = As[r0 + 8][kb + t4 + 4];
            }
#pragma unroll
            for (int j = 0; j < 4; j++) {
                int n0 = wn + j * 8 + g8;
                uint32_t bf0 = Bs[n0][kb + t4];
                uint32_t bf1 = Bs[n0][kb + t4 + 4];
#pragma unroll
                for (int i = 0; i < 4; i++) mma_tf32(acc[i][j], af[i], bf0, bf1);
            }
        }

        if (has_next) {
            __syncthreads();
#pragma unroll
            for (int it = 0; it < 4; it++) {
                int row = it * 32 + lrow;
                uint4 pa = make_uint4(f2tf(sa[it].x), f2tf(sa[it].y), f2tf(sa[it].z), f2tf(sa[it].w));
                uint4 pb = make_uint4(f2tf(sb[it].x), f2tf(sb[it].y), f2tf(sb[it].z), f2tf(sb[it].w));
                *(uint4*)&As[row][lc4] = pa;
                *(uint4*)&Bs[row][lc4] = pb;
            }
            __syncthreads();
        }
    }

    // ---- epilogue ----
    float cs[4][2], cb[4][2], cm[4][2];
    if (mode == 1) {
#pragma unroll
        for (int j = 0; j < 4; j++) {
            int c = tileN + wn + j * 8 + t4 * 2;
#pragma unroll
            for (int q = 0; q < 2; q++) {
                cs[j][q] = gv[c + q] * rsqrtf(vv[c + q] + 1e-5f);
                cb[j][q] = bv[c + q];
                cm[j][q] = mv[c + q];
            }
        }
    }

#pragma unroll
    for (int i = 0; i < 4; i++) {
#pragma unroll
        for (int half = 0; half < 2; half++) {
            int r = tileM + wm + i * 16 + g8 + half * 8;
            if (r >= M) continue;
            float* crow = C + (size_t)r * Ncols;
#pragma unroll
            for (int j = 0; j < 4; j++) {
                int c = tileN + wn + j * 8 + t4 * 2;
                float v0 = acc[i][j][half * 2 + 0];
                float v1 = acc[i][j][half * 2 + 1];
                if (mode == 1) {
                    v0 = fmaxf((v0 - cm[j][0]) * cs[j][0] + cb[j][0], 0.f);
                    v1 = fmaxf((v1 - cm[j][1]) * cs[j][1] + cb[j][1], 0.f);
                }
                if (accum) {
                    float2 old = *(const float2*)(crow + c);
                    v0 += old.x;
                    v1 += old.y;
                }
                *(float2*)(crow + c) = make_float2(v0, v1);
            }
        }
    }
}

// ---------------- host orchestration ----------------
extern "C" void kernel_launch(void* const* d_in, const int* in_sizes, int n_in,
                              void* d_out, int out_size) {
    const float* x  = (const float*)d_in[0];
    const int*   ei = (const int*)d_in[1];
    const float* ea = (const float*)d_in[2];
    int base = 3;
    if (n_in > 19) base = 3 + (n_in - 19);  // skip len0/len1 scalars if present
    const float* l0_src  = (const float*)d_in[base + 0];
    const float* l0_dst  = (const float*)d_in[base + 1];
    const float* l0_edge = (const float*)d_in[base + 2];
    const float* l0_w1   = (const float*)d_in[base + 3];
    const float* l0_g    = (const float*)d_in[base + 4];
    const float* l0_b    = (const float*)d_in[base + 5];
    const float* l0_m    = (const float*)d_in[base + 6];
    const float* l0_v    = (const float*)d_in[base + 7];
    const float* l0_w2   = (const float*)d_in[base + 8];
    const float* l1_edge = (const float*)d_in[base + 9];
    const float* l1_w1   = (const float*)d_in[base + 10];
    const float* l1_g    = (const float*)d_in[base + 11];
    const float* l1_b    = (const float*)d_in[base + 12];
    const float* l1_m    = (const float*)d_in[base + 13];
    const float* l1_v    = (const float*)d_in[base + 14];
    const float* l1_w2   = (const float*)d_in[base + 15];
    float* out = (float*)d_out;

    float *sf, *df, *ob, *hb, *yb, *x1b;
    int *rowptr, *cursor, *eidx;
    cudaGetSymbolAddress((void**)&sf, g_sf);
    cudaGetSymbolAddress((void**)&df, g_df);
    cudaGetSymbolAddress((void**)&ob, g_out);
    cudaGetSymbolAddress((void**)&hb, g_h);
    cudaGetSymbolAddress((void**)&yb, g_y);
    cudaGetSymbolAddress((void**)&x1b, g_x1);
    cudaGetSymbolAddress((void**)&rowptr, g_rowptr);
    cudaGetSymbolAddress((void**)&cursor, g_cursor);
    cudaGetSymbolAddress((void**)&eidx, g_eidx);

    const int offs[2] = {0, LPART};

    // ---- build CSR-by-dst for both edge partitions ----
    for (int p = 0; p < 2; p++) {
        int* rp = rowptr + p * (NN + 1);
        int* cu = cursor + p * NN;
        int* ex = eidx + p * LPART;
        const int* dstp = ei + ETOT + offs[p];
        k_zero_int<<<(NN + 255) / 256, 256>>>(cu, NN);
        k_count_deg<<<(LPART + 255) / 256, 256>>>(dstp, LPART, cu);
        k_scan<<<1, 1024>>>(cu, rp, NN);
        k_copy_int<<<(NN + 255) / 256, 256>>>(rp, cu, NN);
        k_scatter<<<(LPART + 255) / 256, 256>>>(dstp, LPART, cu, ex);
        k_sort_buckets<<<(NN + 127) / 128, 128>>>(rp, ex);
    }

    dim3 blk(256);
    int gy = (NN + BM - 1) / BM;  // 157
    dim3 g512(HC / BN, gy), g1024(H2C / BN, gy);

    // ---- layer 0 ----
    for (int l = 0; l < 2; l++) {
        k_mma_nt<<<g512, blk>>>(x, l0_src + (size_t)l * HC * FINC, sf,
                                NN, HC, FINC, 0, nullptr, nullptr, nullptr, nullptr, 0);
        k_mma_nt<<<g512, blk>>>(x, l0_dst + (size_t)l * HC * FINC, df,
                                NN, HC, FINC, 0, nullptr, nullptr, nullptr, nullptr, 0);
        k_agg<<<(NN + 3) / 4, 128>>>(sf, df, l0_edge + (size_t)l * HC, ea + offs[l],
                                     ei + offs[l], rowptr + l * (NN + 1),
                                     eidx + l * LPART, ob);
        k_mma_nt<<<g1024, blk>>>(ob, l0_w1 + (size_t)l * H2C * HC, hb,
                                 NN, H2C, HC, 1,
                                 l0_g + l * H2C, l0_b + l * H2C,
                                 l0_m + l * H2C, l0_v + l * H2C, 0);
        k_mma_nt<<<g512, blk>>>(hb, l0_w2 + (size_t)l * HC * H2C, yb,
                                NN, HC, H2C, 0, nullptr, nullptr, nullptr, nullptr, l > 0);
    }

    k_leaky<<<(NN * HC + 255) / 256, 256>>>(yb, x1b, NN * HC);

    // ---- layer 1 (no src/dst projections: sf = df = x1) ----
    for (int l = 0; l < 2; l++) {
        k_agg<<<(NN + 3) / 4, 128>>>(x1b, x1b, l1_edge + (size_t)l * HC, ea + offs[l],
                                     ei + offs[l], rowptr + l * (NN + 1),
                                     eidx + l * LPART, ob);
        k_mma_nt<<<g1024, blk>>>(ob, l1_w1 + (size_t)l * H2C * HC, hb,
                                 NN, H2C, HC, 1,
                                 l1_g + l * H2C, l1_b + l * H2C,
                                 l1_m + l * H2C, l1_v + l * H2C, 0);
        k_mma_nt<<<g512, blk>>>(hb, l1_w2 + (size_t)l * HC * H2C, out,
                                NN, HC, H2C, 0, nullptr, nullptr, nullptr, nullptr, l > 0);
    }
}